// round 12
// baseline (speedup 1.0000x reference)
#include <cuda_runtime.h>
#include <math.h>

// ---------------- scratch (device globals: no allocation allowed) ----------
__device__ float g_kf[2 * 512 * 32];            // kf[b][i][c]
__device__ float g_qb[2 * 64 * 512 * 32];       // qb[b][g][j][c]
__device__ float g_out[2 * 64 * 512 * 32];      // out[b][g][j][c] (pre-minmax)

// ---------------- kernel A: kf = k(256->32 proj) + bk ----------------------
// one warp per (b, i); lane = output channel d. Dot accumulated from 0 in
// ascending-c FFMA chain (cublas sgemm style), bias added AFTER (XLA fusion).
__global__ void __launch_bounds__(256) kf_kernel(const float* __restrict__ k,
                                                 const float* __restrict__ Wk,
                                                 const float* __restrict__ bk) {
    int gt   = blockIdx.x * 256 + threadIdx.x;
    int wg   = gt >> 5;                 // 0..1023
    int lane = threadIdx.x & 31;
    int b = wg >> 9;
    int i = wg & 511;
    float acc = 0.0f;
    const float* kp = k + (size_t)b * (256 * 512) + i;
    #pragma unroll 8
    for (int c = 0; c < 256; c++)
        acc = fmaf(kp[(size_t)c * 512], Wk[c * 32 + lane], acc);
    acc = acc + bk[lane];
    g_kf[(b * 512 + i) * 32 + lane] = acc;
}

// ---------------- kernel B: qf = q(32->32 proj)+bq, rearranged to blocks ---
// one warp per (b, j); lane = output channel d. Same rounding discipline.
__global__ void __launch_bounds__(256) qb_kernel(const float* __restrict__ q,
                                                 const float* __restrict__ Wq,
                                                 const float* __restrict__ bq) {
    int gt   = blockIdx.x * 256 + threadIdx.x;
    int wg   = gt >> 5;                 // 0..65535
    int lane = threadIdx.x & 31;
    int b = wg >> 15;
    int j = wg & 32767;                 // flat (h,w,d) with strides 1024,32,1
    int h  = j >> 10;
    int w2 = (j >> 5) & 31;
    int dd = j & 31;
    int g  = ((h >> 3) << 4) | ((w2 >> 3) << 2) | (dd >> 3);
    int jj = ((h & 7) << 6) | ((w2 & 7) << 3) | (dd & 7);
    float acc = 0.0f;
    const float* qp = q + (size_t)b * 32 * 32768 + j;
    #pragma unroll
    for (int c = 0; c < 32; c++)
        acc = fmaf(qp[(size_t)c * 32768], Wq[c * 32 + lane], acc);
    acc = acc + bq[lane];
    g_qb[(((size_t)(b * 64 + g)) * 512 + jj) * 32 + lane] = acc;
}

// ---------------- kernel C: attention per (b,g) -----------------------------
// Numerics strategy: the downstream min-max renorm amplifies absolute error in
// `out` by ~1e5x, and the measured residual (R11) equals the REFERENCE's own
// fp32 rounding noise in its out-einsum. So this kernel REPLICATES the
// reference arithmetic so rounding correlates and cancels in the diff:
//   sim  = fl(dot / denom)            (__fdiv_rn; dot = ascending-c FFMA chain)
//   e    = expf(fl(sim - rowmax))     (softmax materialized like jax.nn.softmax)
//   s    = sum(e) in XLA row-reduce order (lane-serial stride-32, shfl_down tree)
//   att  = fl(e / s)                  (__fdiv_rn, materialized)
//   out  = ascending-i single-accumulator FFMA chain of att*qb (cublas k-loop)
//
// smem layout (floats):
//   kfT  [0,      16416)  : kfT[c*513 + i]   (padded, conflict-free)
//   qbs  [16416,  +16384) : qb[j*32 + c]
//   esh  [32800,  +16384) : per-warp att rows, warp w: [w*1024, +1024)
//   misc [49184,  +64)    : misc[0]=denom, misc[32+c]=norm products
#define ATTN_SMEM_FLOATS 49248

__global__ void __launch_bounds__(512, 1) attn_kernel() {
    extern __shared__ float sh[];
    float* kfT  = sh;
    float* qbs  = sh + 16416;
    float* esh  = sh + 32800;
    float* misc = sh + 49184;

    int bid  = blockIdx.x;          // b*64 + g
    int b    = bid >> 6;
    int tid  = threadIdx.x;
    int w    = tid >> 5;
    int lane = tid & 31;

    const float* gq = g_qb + (size_t)bid * 16384;
    const float* gk = g_kf + (size_t)b * 16384;
    for (int idx = tid; idx < 16384; idx += 512) qbs[idx] = gq[idx];
    for (int idx = tid; idx < 16384; idx += 512) {
        int i = idx >> 5, c = idx & 31;
        kfT[c * 513 + i] = gk[idx];
    }
    __syncthreads();

    // ---- denom = sum_c ||kf[:,c]|| * ||qb[:,c]|| + eps ----
    // (denom bits are non-critical: exp output granularity washes them out)
    {
        int base = w * 32;
        float sq = 0.f;
        #pragma unroll 8
        for (int t = 0; t < 32; t++) { float v = qbs[(base + t) * 32 + lane]; sq = fmaf(v, v, sq); }
        esh[w * 32 + lane] = sq;
        float sk = 0.f;
        #pragma unroll 8
        for (int t = 0; t < 32; t++) { float v = kfT[lane * 513 + base + t]; sk = fmaf(v, v, sk); }
        esh[512 + w * 32 + lane] = sk;
    }
    __syncthreads();
    if (tid < 32) {
        float qn2 = 0.f, kn2 = 0.f;
        #pragma unroll
        for (int ww = 0; ww < 16; ww++) {
            qn2 += esh[ww * 32 + lane];
            kn2 += esh[512 + ww * 32 + lane];
        }
        misc[32 + lane] = sqrtf(kn2) * sqrtf(qn2);
    }
    __syncthreads();
    if (tid == 0) {
        float d = 0.f;
        #pragma unroll
        for (int c = 0; c < 32; c++) d = d + misc[32 + c];   // ascending-c serial
        misc[0] = d + 1e-4f;
    }
    __syncthreads();
    const float denomv = misc[0];

    float* ew = esh + w * 1024;
    float* og = g_out + (size_t)bid * 16384;

    for (int it = 0; it < 16; it++) {
        int ja = w * 32 + it * 2;
        int jb2 = ja + 1;
        float acc0[16], acc1[16];
        #pragma unroll
        for (int t = 0; t < 16; t++) { acc0[t] = 0.f; acc1[t] = 0.f; }

        // phase 1: sim dots for j=ja,jb2 ; lane covers i = lane + 32t
        const float* qa = qbs + ja * 32;
        const float* qb2 = qbs + jb2 * 32;
        #pragma unroll 4
        for (int c = 0; c < 32; c++) {
            float qv0 = qa[c];
            float qv1 = qb2[c];
            const float* kp = kfT + c * 513 + lane;
            #pragma unroll
            for (int t = 0; t < 16; t++) {
                float kv = kp[32 * t];
                acc0[t] = fmaf(qv0, kv, acc0[t]);
                acc1[t] = fmaf(qv1, kv, acc1[t]);
            }
        }

        // sim = fl(dot / denom)  (elementwise division, correctly rounded)
        #pragma unroll
        for (int t = 0; t < 16; t++) {
            acc0[t] = __fdiv_rn(acc0[t], denomv);
            acc1[t] = __fdiv_rn(acc1[t], denomv);
        }

        // row max (exact, order-free)
        float m0 = -1e30f, m1 = -1e30f;
        #pragma unroll
        for (int t = 0; t < 16; t++) { m0 = fmaxf(m0, acc0[t]); m1 = fmaxf(m1, acc1[t]); }
        #pragma unroll
        for (int o = 16; o > 0; o >>= 1) {
            m0 = fmaxf(m0, __shfl_xor_sync(0xffffffffu, m0, o));
            m1 = fmaxf(m1, __shfl_xor_sync(0xffffffffu, m1, o));
        }

        // e = expf(sim - max); lane-serial ascending sum (stride-32 elements)
        float s0 = 0.f, s1 = 0.f;
        #pragma unroll
        for (int t = 0; t < 16; t++) {
            float e0 = expf(acc0[t] - m0);
            float e1 = expf(acc1[t] - m1);
            acc0[t] = e0;
            acc1[t] = e1;
            s0 = s0 + e0;
            s1 = s1 + e1;
        }
        // XLA-style warp reduce: acc = acc + shfl_down(acc, off), off=16..1
        #pragma unroll
        for (int o = 16; o > 0; o >>= 1) {
            s0 = s0 + __shfl_down_sync(0xffffffffu, s0, o);
            s1 = s1 + __shfl_down_sync(0xffffffffu, s1, o);
        }
        s0 = __shfl_sync(0xffffffffu, s0, 0);
        s1 = __shfl_sync(0xffffffffu, s1, 0);

        // att = fl(e / s), materialized to shared
        #pragma unroll
        for (int t = 0; t < 16; t++) {
            ew[lane + 32 * t]       = __fdiv_rn(acc0[t], s0);
            ew[512 + lane + 32 * t] = __fdiv_rn(acc1[t], s1);
        }
        __syncwarp();

        // phase 2: out[j][c] = ascending-i FFMA chain of att_i * qb[i][c]
        float o0 = 0.f, o1 = 0.f;
        const float4* e0p = (const float4*)ew;
        const float4* e1p = (const float4*)(ew + 512);
        #pragma unroll 4
        for (int i4 = 0; i4 < 128; i4++) {
            float4 e0 = e0p[i4];
            float4 e1 = e1p[i4];
            const float* qp = qbs + i4 * 128 + lane;
            float q0 = qp[0], q1 = qp[32], q2 = qp[64], q3 = qp[96];
            o0 = fmaf(e0.x, q0, o0); o1 = fmaf(e1.x, q0, o1);
            o0 = fmaf(e0.y, q1, o0); o1 = fmaf(e1.y, q1, o1);
            o0 = fmaf(e0.z, q2, o0); o1 = fmaf(e1.z, q2, o1);
            o0 = fmaf(e0.w, q3, o0); o1 = fmaf(e1.w, q3, o1);
        }
        og[ja * 32 + lane]  = o0;
        og[jb2 * 32 + lane] = o1;
        __syncwarp();   // done reading ew before next iteration overwrites it
    }
}

// ---------------- kernel D: min-max renorm + scramble + Wp proj ------------
// smem: v[16384], red[1024], mnv[32], dnv[32], wps[1024], bps[32]
#define FIN_SMEM_FLOATS 18528

__global__ void __launch_bounds__(512, 1) final_kernel(const float* __restrict__ Wp,
                                                       const float* __restrict__ bp,
                                                       float* __restrict__ outF) {
    extern __shared__ float sh[];
    float* v   = sh;            // 16384
    float* red = sh + 16384;    // 1024
    float* mnv = sh + 17408;    // 32
    float* dnv = sh + 17440;    // 32  (range + eps, used as DIVISOR)
    float* wps = sh + 17472;    // 1024
    float* bps = sh + 18496;    // 32

    int bid  = blockIdx.x;
    int b    = bid >> 6;
    int g    = bid & 63;
    int tid  = threadIdx.x;
    int w    = tid >> 5;
    int lane = tid & 31;

    const float* go = g_out + (size_t)bid * 16384;
    for (int idx = tid; idx < 16384; idx += 512) v[idx] = go[idx];
    for (int idx = tid; idx < 1024; idx += 512) wps[idx] = Wp[idx];
    if (tid < 32) bps[tid] = bp[tid];
    __syncthreads();

    // per-channel min/max over the 512 positions (exact, order-free)
    float mn = 1e30f, mx = -1e30f;
    #pragma unroll 8
    for (int t = 0; t < 32; t++) {
        float x = v[(w * 32 + t) * 32 + lane];
        mn = fminf(mn, x);
        mx = fmaxf(mx, x);
    }
    red[w * 32 + lane] = mn;
    red[512 + w * 32 + lane] = mx;
    __syncthreads();
    if (tid < 32) {
        float a = 1e30f, bb = -1e30f;
        #pragma unroll
        for (int ww = 0; ww < 16; ww++) {
            a  = fminf(a,  red[ww * 32 + lane]);
            bb = fmaxf(bb, red[512 + ww * 32 + lane]);
        }
        mnv[lane] = a;
        dnv[lane] = (bb - a) + 1e-4f;
    }
    __syncthreads();
    for (int idx = tid; idx < 16384; idx += 512) {
        int c = idx & 31;
        v[idx] = __fdiv_rn(v[idx] - mnv[c], dnv[c]);   // fl((out-mn)/(range+eps))
    }
    __syncthreads();

    // scramble + projection. output (ih,iw,id,c') reads v[j'][cidx]:
    //   cidx = ih*4 + (iw>>1),  j' = (iw&1)*256 + id*32 + c'
    int bh = g >> 4, bw = (g >> 2) & 3, bd = g & 3;
    float wcol[32];
    #pragma unroll
    for (int c = 0; c < 32; c++) wcol[c] = wps[c * 32 + lane];
    float bpv = bps[lane];

    for (int p = 0; p < 4; p++) {
        int pair = w * 4 + p;           // 0..63 -> (ih, iw)
        int ih = pair >> 3, iw = pair & 7;
        int cidx = ih * 4 + (iw >> 1);
        int joff = (iw & 1) * 256;
        int h  = bh * 8 + ih;
        int w2 = bw * 8 + iw;
        size_t obase = ((size_t)(b * 32 + lane)) * 32768 + h * 1024 + w2 * 32 + bd * 8;
        #pragma unroll
        for (int id = 0; id < 8; id++) {
            float acc = 0.0f;
            const float* vp = v + (joff + id * 32) * 32 + cidx;
            #pragma unroll
            for (int c = 0; c < 32; c++)
                acc = fmaf(vp[c * 32], wcol[c], acc);
            acc = acc + bpv;            // bias added AFTER the dot (XLA order)
            outF[obase + id] = acc;
        }
    }
}

// ---------------- launch ----------------------------------------------------
extern "C" void kernel_launch(void* const* d_in, const int* in_sizes, int n_in,
                              void* d_out, int out_size) {
    const float* q  = (const float*)d_in[0];
    const float* k  = (const float*)d_in[1];
    const float* Wq = (const float*)d_in[2];
    const float* bq = (const float*)d_in[3];
    const float* Wk = (const float*)d_in[4];
    const float* bk = (const float*)d_in[5];
    const float* Wp = (const float*)d_in[6];
    const float* bp = (const float*)d_in[7];
    float* out = (float*)d_out;

    cudaFuncSetAttribute(attn_kernel, cudaFuncAttributeMaxDynamicSharedMemorySize,
                         ATTN_SMEM_FLOATS * (int)sizeof(float));
    cudaFuncSetAttribute(final_kernel, cudaFuncAttributeMaxDynamicSharedMemorySize,
                         FIN_SMEM_FLOATS * (int)sizeof(float));

    kf_kernel<<<128, 256>>>(k, Wk, bk);
    qb_kernel<<<8192, 256>>>(q, Wq, bq);
    attn_kernel<<<128, 512, ATTN_SMEM_FLOATS * sizeof(float)>>>();
    final_kernel<<<128, 512, FIN_SMEM_FLOATS * sizeof(float)>>>(Wp, bp, out);
}

// round 13
// speedup vs baseline: 1.0021x; 1.0021x over previous
#include <cuda_runtime.h>
#include <math.h>

// ---------------- scratch (device globals: no allocation allowed) ----------
__device__ float g_kf[2 * 512 * 32];            // kf[b][i][c]
__device__ float g_qb[2 * 64 * 512 * 32];       // qb[b][g][j][c]
__device__ float g_out[2 * 64 * 512 * 32];      // out[b][g][j][c] (pre-minmax)

// ---------------- kernel A: kf = k(256->32 proj) + bk ----------------------
// one warp per (b, i); lane = output channel d. Dot accumulated from 0 in
// ascending-c FFMA chain (cublas sgemm style), bias added AFTER (XLA fusion).
__global__ void __launch_bounds__(256) kf_kernel(const float* __restrict__ k,
                                                 const float* __restrict__ Wk,
                                                 const float* __restrict__ bk) {
    int gt   = blockIdx.x * 256 + threadIdx.x;
    int wg   = gt >> 5;                 // 0..1023
    int lane = threadIdx.x & 31;
    int b = wg >> 9;
    int i = wg & 511;
    float acc = 0.0f;
    const float* kp = k + (size_t)b * (256 * 512) + i;
    #pragma unroll 8
    for (int c = 0; c < 256; c++)
        acc = fmaf(kp[(size_t)c * 512], Wk[c * 32 + lane], acc);
    acc = acc + bk[lane];
    g_kf[(b * 512 + i) * 32 + lane] = acc;
}

// ---------------- kernel B: qf = q(32->32 proj)+bq, rearranged to blocks ---
// one warp per (b, j); lane = output channel d. Same rounding discipline.
__global__ void __launch_bounds__(256) qb_kernel(const float* __restrict__ q,
                                                 const float* __restrict__ Wq,
                                                 const float* __restrict__ bq) {
    int gt   = blockIdx.x * 256 + threadIdx.x;
    int wg   = gt >> 5;                 // 0..65535
    int lane = threadIdx.x & 31;
    int b = wg >> 15;
    int j = wg & 32767;                 // flat (h,w,d) with strides 1024,32,1
    int h  = j >> 10;
    int w2 = (j >> 5) & 31;
    int dd = j & 31;
    int g  = ((h >> 3) << 4) | ((w2 >> 3) << 2) | (dd >> 3);
    int jj = ((h & 7) << 6) | ((w2 & 7) << 3) | (dd & 7);
    float acc = 0.0f;
    const float* qp = q + (size_t)b * 32 * 32768 + j;
    #pragma unroll
    for (int c = 0; c < 32; c++)
        acc = fmaf(qp[(size_t)c * 32768], Wq[c * 32 + lane], acc);
    acc = acc + bq[lane];
    g_qb[(((size_t)(b * 64 + g)) * 512 + jj) * 32 + lane] = acc;
}

// ---------------- kernel C: attention per (b,g) -----------------------------
// Numerics strategy: the downstream min-max renorm amplifies absolute error in
// `out` by ~1e5x, and the measured residual (R11) equals the REFERENCE's own
// fp32 rounding noise in its out-einsum. So this kernel REPLICATES the
// reference arithmetic so rounding correlates and cancels in the diff:
//   sim  = fl(dot / denom)            (__fdiv_rn; dot = ascending-c FFMA chain)
//   e    = expf(fl(sim - rowmax))     (softmax materialized like jax.nn.softmax)
//   s    = sum(e) in XLA row-reduce order (lane-serial stride-32, shfl_down tree)
//   att  = fl(e / s)                  (__fdiv_rn, materialized)
//   out  = ascending-i single-accumulator FFMA chain of att*qb (cublas k-loop)
//
// smem layout (floats):
//   kfT  [0,      16416)  : kfT[c*513 + i]   (padded, conflict-free)
//   qbs  [16416,  +16384) : qb[j*32 + c]
//   esh  [32800,  +16384) : per-warp att rows, warp w: [w*1024, +1024)
//   misc [49184,  +64)    : misc[0]=denom, misc[32+c]=norm products
#define ATTN_SMEM_FLOATS 49248

__global__ void __launch_bounds__(512, 1) attn_kernel() {
    extern __shared__ float sh[];
    float* kfT  = sh;
    float* qbs  = sh + 16416;
    float* esh  = sh + 32800;
    float* misc = sh + 49184;

    int bid  = blockIdx.x;          // b*64 + g
    int b    = bid >> 6;
    int tid  = threadIdx.x;
    int w    = tid >> 5;
    int lane = tid & 31;

    const float* gq = g_qb + (size_t)bid * 16384;
    const float* gk = g_kf + (size_t)b * 16384;
    for (int idx = tid; idx < 16384; idx += 512) qbs[idx] = gq[idx];
    for (int idx = tid; idx < 16384; idx += 512) {
        int i = idx >> 5, c = idx & 31;
        kfT[c * 513 + i] = gk[idx];
    }
    __syncthreads();

    // ---- denom = sum_c ||kf[:,c]|| * ||qb[:,c]|| + eps ----
    // (denom bits are non-critical: exp output granularity washes them out)
    {
        int base = w * 32;
        float sq = 0.f;
        #pragma unroll 8
        for (int t = 0; t < 32; t++) { float v = qbs[(base + t) * 32 + lane]; sq = fmaf(v, v, sq); }
        esh[w * 32 + lane] = sq;
        float sk = 0.f;
        #pragma unroll 8
        for (int t = 0; t < 32; t++) { float v = kfT[lane * 513 + base + t]; sk = fmaf(v, v, sk); }
        esh[512 + w * 32 + lane] = sk;
    }
    __syncthreads();
    if (tid < 32) {
        float qn2 = 0.f, kn2 = 0.f;
        #pragma unroll
        for (int ww = 0; ww < 16; ww++) {
            qn2 += esh[ww * 32 + lane];
            kn2 += esh[512 + ww * 32 + lane];
        }
        misc[32 + lane] = sqrtf(kn2) * sqrtf(qn2);
    }
    __syncthreads();
    if (tid == 0) {
        float d = 0.f;
        #pragma unroll
        for (int c = 0; c < 32; c++) d = d + misc[32 + c];   // ascending-c serial
        misc[0] = d + 1e-4f;
    }
    __syncthreads();
    const float denomv = misc[0];

    float* ew = esh + w * 1024;
    float* og = g_out + (size_t)bid * 16384;

    for (int it = 0; it < 16; it++) {
        int ja = w * 32 + it * 2;
        int jb2 = ja + 1;
        float acc0[16], acc1[16];
        #pragma unroll
        for (int t = 0; t < 16; t++) { acc0[t] = 0.f; acc1[t] = 0.f; }

        // phase 1: sim dots for j=ja,jb2 ; lane covers i = lane + 32t
        const float* qa = qbs + ja * 32;
        const float* qb2 = qbs + jb2 * 32;
        #pragma unroll 4
        for (int c = 0; c < 32; c++) {
            float qv0 = qa[c];
            float qv1 = qb2[c];
            const float* kp = kfT + c * 513 + lane;
            #pragma unroll
            for (int t = 0; t < 16; t++) {
                float kv = kp[32 * t];
                acc0[t] = fmaf(qv0, kv, acc0[t]);
                acc1[t] = fmaf(qv1, kv, acc1[t]);
            }
        }

        // sim = fl(dot / denom)  (elementwise division, correctly rounded)
        #pragma unroll
        for (int t = 0; t < 16; t++) {
            acc0[t] = __fdiv_rn(acc0[t], denomv);
            acc1[t] = __fdiv_rn(acc1[t], denomv);
        }

        // row max (exact, order-free)
        float m0 = -1e30f, m1 = -1e30f;
        #pragma unroll
        for (int t = 0; t < 16; t++) { m0 = fmaxf(m0, acc0[t]); m1 = fmaxf(m1, acc1[t]); }
        #pragma unroll
        for (int o = 16; o > 0; o >>= 1) {
            m0 = fmaxf(m0, __shfl_xor_sync(0xffffffffu, m0, o));
            m1 = fmaxf(m1, __shfl_xor_sync(0xffffffffu, m1, o));
        }

        // e = expf(sim - max); lane-serial ascending sum (stride-32 elements)
        float s0 = 0.f, s1 = 0.f;
        #pragma unroll
        for (int t = 0; t < 16; t++) {
            float e0 = expf(acc0[t] - m0);
            float e1 = expf(acc1[t] - m1);
            acc0[t] = e0;
            acc1[t] = e1;
            s0 = s0 + e0;
            s1 = s1 + e1;
        }
        // XLA-style warp reduce: acc = acc + shfl_down(acc, off), off=16..1
        #pragma unroll
        for (int o = 16; o > 0; o >>= 1) {
            s0 = s0 + __shfl_down_sync(0xffffffffu, s0, o);
            s1 = s1 + __shfl_down_sync(0xffffffffu, s1, o);
        }
        s0 = __shfl_sync(0xffffffffu, s0, 0);
        s1 = __shfl_sync(0xffffffffu, s1, 0);

        // att = fl(e / s), materialized to shared
        #pragma unroll
        for (int t = 0; t < 16; t++) {
            ew[lane + 32 * t]       = __fdiv_rn(acc0[t], s0);
            ew[512 + lane + 32 * t] = __fdiv_rn(acc1[t], s1);
        }
        __syncwarp();

        // phase 2: out[j][c] = ascending-i FFMA chain of att_i * qb[i][c]
        float o0 = 0.f, o1 = 0.f;
        const float4* e0p = (const float4*)ew;
        const float4* e1p = (const float4*)(ew + 512);
        #pragma unroll 4
        for (int i4 = 0; i4 < 128; i4++) {
            float4 e0 = e0p[i4];
            float4 e1 = e1p[i4];
            const float* qp = qbs + i4 * 128 + lane;
            float q0 = qp[0], q1 = qp[32], q2 = qp[64], q3 = qp[96];
            o0 = fmaf(e0.x, q0, o0); o1 = fmaf(e1.x, q0, o1);
            o0 = fmaf(e0.y, q1, o0); o1 = fmaf(e1.y, q1, o1);
            o0 = fmaf(e0.z, q2, o0); o1 = fmaf(e1.z, q2, o1);
            o0 = fmaf(e0.w, q3, o0); o1 = fmaf(e1.w, q3, o1);
        }
        og[ja * 32 + lane]  = o0;
        og[jb2 * 32 + lane] = o1;
        __syncwarp();   // done reading ew before next iteration overwrites it
    }
}

// ---------------- kernel D: min-max renorm + scramble + Wp proj ------------
// smem: v[16384], red[1024], mnv[32], dnv[32], wps[1024], bps[32]
#define FIN_SMEM_FLOATS 18528

__global__ void __launch_bounds__(512, 1) final_kernel(const float* __restrict__ Wp,
                                                       const float* __restrict__ bp,
                                                       float* __restrict__ outF) {
    extern __shared__ float sh[];
    float* v   = sh;            // 16384
    float* red = sh + 16384;    // 1024
    float* mnv = sh + 17408;    // 32
    float* dnv = sh + 17440;    // 32  (range + eps, used as DIVISOR)
    float* wps = sh + 17472;    // 1024
    float* bps = sh + 18496;    // 32

    int bid  = blockIdx.x;
    int b    = bid >> 6;
    int g    = bid & 63;
    int tid  = threadIdx.x;
    int w    = tid >> 5;
    int lane = tid & 31;

    const float* go = g_out + (size_t)bid * 16384;
    for (int idx = tid; idx < 16384; idx += 512) v[idx] = go[idx];
    for (int idx = tid; idx < 1024; idx += 512) wps[idx] = Wp[idx];
    if (tid < 32) bps[tid] = bp[tid];
    __syncthreads();

    // per-channel min/max over the 512 positions (exact, order-free)
    float mn = 1e30f, mx = -1e30f;
    #pragma unroll 8
    for (int t = 0; t < 32; t++) {
        float x = v[(w * 32 + t) * 32 + lane];
        mn = fminf(mn, x);
        mx = fmaxf(mx, x);
    }
    red[w * 32 + lane] = mn;
    red[512 + w * 32 + lane] = mx;
    __syncthreads();
    if (tid < 32) {
        float a = 1e30f, bb = -1e30f;
        #pragma unroll
        for (int ww = 0; ww < 16; ww++) {
            a  = fminf(a,  red[ww * 32 + lane]);
            bb = fmaxf(bb, red[512 + ww * 32 + lane]);
        }
        mnv[lane] = a;
        dnv[lane] = (bb - a) + 1e-4f;
    }
    __syncthreads();
    for (int idx = tid; idx < 16384; idx += 512) {
        int c = idx & 31;
        v[idx] = __fdiv_rn(v[idx] - mnv[c], dnv[c]);   // fl((out-mn)/(range+eps))
    }
    __syncthreads();

    // scramble + projection. output (ih,iw,id,c') reads v[j'][cidx]:
    //   cidx = ih*4 + (iw>>1),  j' = (iw&1)*256 + id*32 + c'
    int bh = g >> 4, bw = (g >> 2) & 3, bd = g & 3;
    float wcol[32];
    #pragma unroll
    for (int c = 0; c < 32; c++) wcol[c] = wps[c * 32 + lane];
    float bpv = bps[lane];

    for (int p = 0; p < 4; p++) {
        int pair = w * 4 + p;           // 0..63 -> (ih, iw)
        int ih = pair >> 3, iw = pair & 7;
        int cidx = ih * 4 + (iw >> 1);
        int joff = (iw & 1) * 256;
        int h  = bh * 8 + ih;
        int w2 = bw * 8 + iw;
        size_t obase = ((size_t)(b * 32 + lane)) * 32768 + h * 1024 + w2 * 32 + bd * 8;
        #pragma unroll
        for (int id = 0; id < 8; id++) {
            float acc = 0.0f;
            const float* vp = v + (joff + id * 32) * 32 + cidx;
            #pragma unroll
            for (int c = 0; c < 32; c++)
                acc = fmaf(vp[c * 32], wcol[c], acc);
            acc = acc + bpv;            // bias added AFTER the dot (XLA order)
            outF[obase + id] = acc;
        }
    }
}

// ---------------- launch ----------------------------------------------------
extern "C" void kernel_launch(void* const* d_in, const int* in_sizes, int n_in,
                              void* d_out, int out_size) {
    const float* q  = (const float*)d_in[0];
    const float* k  = (const float*)d_in[1];
    const float* Wq = (const float*)d_in[2];
    const float* bq = (const float*)d_in[3];
    const float* Wk = (const float*)d_in[4];
    const float* bk = (const float*)d_in[5];
    const float* Wp = (const float*)d_in[6];
    const float* bp = (const float*)d_in[7];
    float* out = (float*)d_out;

    cudaFuncSetAttribute(attn_kernel, cudaFuncAttributeMaxDynamicSharedMemorySize,
                         ATTN_SMEM_FLOATS * (int)sizeof(float));
    cudaFuncSetAttribute(final_kernel, cudaFuncAttributeMaxDynamicSharedMemorySize,
                         FIN_SMEM_FLOATS * (int)sizeof(float));

    kf_kernel<<<128, 256>>>(k, Wk, bk);
    qb_kernel<<<8192, 256>>>(q, Wq, bq);
    attn_kernel<<<128, 512, ATTN_SMEM_FLOATS * sizeof(float)>>>();
    final_kernel<<<128, 512, FIN_SMEM_FLOATS * sizeof(float)>>>(Wp, bp, out);
}